// round 3
// baseline (speedup 1.0000x reference)
#include <cuda_runtime.h>

#define NN 50000
#define NE 800000
#define DIN 128
#define NC 40

// ---- scratch (device globals; no allocation) ----
__device__ int   g_is64;
__device__ int   g_deg[NN];
__device__ int   g_row[NN + 1];
__device__ int   g_cur[NN];
__device__ int   g_src[NE];
__device__ float g_agg1[(size_t)NN * DIN];   // scatter-mean(x)
__device__ float g_h[(size_t)NN * DIN];      // relu(layer1)
__device__ float g_C[(size_t)NN * 80];       // [A | R] = h @ [W2_l | W2_r]

// ---------------- dtype detection for edge_index ----------------
// If int64: odd 32-bit words (high halves of nonnegative <2^31 values) are all 0.
// If int32: they are random indices; 4096 all-zero is impossible in practice.
__global__ void k_detect(const int* __restrict__ w) {
    __shared__ int any;
    if (threadIdx.x == 0) any = 0;
    __syncthreads();
    for (int i = threadIdx.x; i < 4096; i += blockDim.x) {
        if (w[2 * i + 1] != 0) any = 1;   // within first 8192 ints < 2*NE, always in-bounds
    }
    __syncthreads();
    if (threadIdx.x == 0) g_is64 = (any == 0) ? 1 : 0;
}

__device__ __forceinline__ int load_idx(const void* eiv, long long pos) {
    int v;
    if (g_is64) v = (int)((const long long*)eiv)[pos];
    else        v = ((const int*)eiv)[pos];
    v = v < 0 ? 0 : (v >= NN ? NN - 1 : v);
    return v;
}

// ---------------- CSR build ----------------
__global__ void k_zero() {
    int i = blockIdx.x * blockDim.x + threadIdx.x;
    if (i < NN) g_deg[i] = 0;
}

__global__ void k_hist(const void* __restrict__ eiv) {
    int e = blockIdx.x * blockDim.x + threadIdx.x;
    if (e < NE) {
        int d = load_idx(eiv, (long long)NE + e);   // dst row of edge_index [2, E]
        atomicAdd(&g_deg[d], 1);
    }
}

// single-block exclusive scan over 50000 degrees -> row offsets + cursor copy
__global__ void k_scan() {
    __shared__ int sums[1024];
    int t = threadIdx.x;
    const int CH = (NN + 1023) / 1024;   // 49
    int start = t * CH;
    int end = start + CH; if (end > NN) end = NN; if (start > NN) start = NN;
    int s = 0;
    for (int i = start; i < end; i++) s += g_deg[i];
    sums[t] = s;
    __syncthreads();
    // inclusive Hillis-Steele scan
    for (int off = 1; off < 1024; off <<= 1) {
        int v = (t >= off) ? sums[t - off] : 0;
        __syncthreads();
        sums[t] += v;
        __syncthreads();
    }
    int pref = (t == 0) ? 0 : sums[t - 1];
    for (int i = start; i < end; i++) {
        g_row[i] = pref;
        g_cur[i] = pref;
        pref += g_deg[i];
    }
    if (t == 1023) g_row[NN] = sums[1023];
}

__global__ void k_scatter(const void* __restrict__ eiv) {
    int e = blockIdx.x * blockDim.x + threadIdx.x;
    if (e < NE) {
        int srcv = load_idx(eiv, e);
        int d    = load_idx(eiv, (long long)NE + e);
        int pos = atomicAdd(&g_cur[d], 1);
        g_src[pos] = srcv;
    }
}

// ---------------- layer-1 aggregation: agg1 = scatter-mean(x) ----------------
__global__ void k_agg1(const float* __restrict__ x) {
    int gt = blockIdx.x * blockDim.x + threadIdx.x;
    int w = gt >> 5;
    int lane = gt & 31;
    if (w >= NN) return;
    int s0 = g_row[w], s1 = g_row[w + 1];
    const float4* X = (const float4*)x;
    float4 acc = make_float4(0.f, 0.f, 0.f, 0.f);
    int i = s0;
    for (; i + 2 <= s1; i += 2) {
        int sa = g_src[i], sb = g_src[i + 1];
        float4 a = X[(size_t)sa * 32 + lane];
        float4 b = X[(size_t)sb * 32 + lane];
        acc.x += a.x; acc.y += a.y; acc.z += a.z; acc.w += a.w;
        acc.x += b.x; acc.y += b.y; acc.z += b.z; acc.w += b.w;
    }
    if (i < s1) {
        int sa = g_src[i];
        float4 a = X[(size_t)sa * 32 + lane];
        acc.x += a.x; acc.y += a.y; acc.z += a.z; acc.w += a.w;
    }
    int cnt = s1 - s0; if (cnt < 1) cnt = 1;
    float sc = 1.0f / (float)cnt;
    float4 o = make_float4(acc.x * sc, acc.y * sc, acc.z * sc, acc.w * sc);
    ((float4*)g_agg1)[(size_t)w * 32 + lane] = o;
}

// ---------------- GEMM1: h = relu([agg1 | x] @ [W1_l ; W1_r] + b1) ----------------
// BM=64, BN=128 (full), BK=16, 256 threads, thread tile 4x8
__global__ __launch_bounds__(256) void k_gemm1(const float* __restrict__ x,
                                               const float* __restrict__ W1l,
                                               const float* __restrict__ W1r,
                                               const float* __restrict__ b1) {
    __shared__ float As[16][64];
    __shared__ float Bs[16][128];
    int t = threadIdx.x;
    int bm = blockIdx.x * 64;
    int ty = t >> 4;        // 0..15 (row group)
    int tx = t & 15;        // 0..15 (col group)

    float acc[4][8];
#pragma unroll
    for (int i = 0; i < 4; i++)
#pragma unroll
        for (int j = 0; j < 8; j++) acc[i][j] = 0.f;

    int arow = t >> 2, aq = t & 3;
    int am = bm + arow; if (am >= NN) am = NN - 1;

    for (int k0 = 0; k0 < 256; k0 += 16) {
        // A tile load (64 x 16), store k-major
        {
            int kg = k0 + aq * 4;
            const float* ap = (kg < 128) ? (g_agg1 + (size_t)am * 128 + kg)
                                         : (x + (size_t)am * 128 + (kg - 128));
            float4 av = *(const float4*)ap;
            As[aq * 4 + 0][arow] = av.x;
            As[aq * 4 + 1][arow] = av.y;
            As[aq * 4 + 2][arow] = av.z;
            As[aq * 4 + 3][arow] = av.w;
        }
        // B tile load (16 x 128)
#pragma unroll
        for (int r = 0; r < 2; r++) {
            int s = t + r * 256;
            int kr = s >> 5;
            int c = (s & 31) * 4;
            int kg = k0 + kr;
            const float* bp = (kg < 128) ? (W1l + (size_t)kg * 128 + c)
                                         : (W1r + (size_t)(kg - 128) * 128 + c);
            *(float4*)&Bs[kr][c] = *(const float4*)bp;
        }
        __syncthreads();
#pragma unroll
        for (int kk = 0; kk < 16; kk++) {
            float4 a = *(const float4*)&As[kk][ty * 4];
            float4 bb0 = *(const float4*)&Bs[kk][tx * 8];
            float4 bb1 = *(const float4*)&Bs[kk][tx * 8 + 4];
            float av[4] = {a.x, a.y, a.z, a.w};
            float bv[8] = {bb0.x, bb0.y, bb0.z, bb0.w, bb1.x, bb1.y, bb1.z, bb1.w};
#pragma unroll
            for (int i = 0; i < 4; i++)
#pragma unroll
                for (int j = 0; j < 8; j++) acc[i][j] += av[i] * bv[j];
        }
        __syncthreads();
    }

    // epilogue: +b1, relu, store
    int c0 = tx * 8;
    float bias[8];
#pragma unroll
    for (int j = 0; j < 8; j++) bias[j] = b1[c0 + j];
#pragma unroll
    for (int i = 0; i < 4; i++) {
        int m = bm + ty * 4 + i;
        if (m >= NN) break;
        float4 o0, o1;
        o0.x = fmaxf(acc[i][0] + bias[0], 0.f);
        o0.y = fmaxf(acc[i][1] + bias[1], 0.f);
        o0.z = fmaxf(acc[i][2] + bias[2], 0.f);
        o0.w = fmaxf(acc[i][3] + bias[3], 0.f);
        o1.x = fmaxf(acc[i][4] + bias[4], 0.f);
        o1.y = fmaxf(acc[i][5] + bias[5], 0.f);
        o1.z = fmaxf(acc[i][6] + bias[6], 0.f);
        o1.w = fmaxf(acc[i][7] + bias[7], 0.f);
        *(float4*)&g_h[(size_t)m * 128 + c0] = o0;
        *(float4*)&g_h[(size_t)m * 128 + c0 + 4] = o1;
    }
}

// ---------------- GEMM2: C = h @ [W2_l | W2_r]  ([50k,128]@[128,80]) ----------------
// BM=64, BN=80 (full), BK=16, 160 threads, thread tile 4x8
__global__ __launch_bounds__(160) void k_gemm2(const float* __restrict__ W2l,
                                               const float* __restrict__ W2r) {
    __shared__ float As[16][64];
    __shared__ float Bs[16][80];
    int t = threadIdx.x;
    int bm = blockIdx.x * 64;
    int ty = t / 10;        // 0..15
    int tx = t % 10;        // 0..9

    float acc[4][8];
#pragma unroll
    for (int i = 0; i < 4; i++)
#pragma unroll
        for (int j = 0; j < 8; j++) acc[i][j] = 0.f;

    for (int k0 = 0; k0 < 128; k0 += 16) {
        // A tile: 64 rows x 16 k = 256 float4-slots
        for (int s = t; s < 256; s += 160) {
            int row = s >> 2, q = s & 3;
            int m = bm + row; if (m >= NN) m = NN - 1;
            int kg = k0 + q * 4;
            float4 av = *(const float4*)(g_h + (size_t)m * 128 + kg);
            As[q * 4 + 0][row] = av.x;
            As[q * 4 + 1][row] = av.y;
            As[q * 4 + 2][row] = av.z;
            As[q * 4 + 3][row] = av.w;
        }
        // B tile: 16 k x 80 cols = 320 float4-slots
        for (int s = t; s < 320; s += 160) {
            int kr = s / 20;
            int c = (s % 20) * 4;
            int kg = k0 + kr;
            const float* bp = (c < 40) ? (W2l + (size_t)kg * 40 + c)
                                       : (W2r + (size_t)kg * 40 + (c - 40));
            *(float4*)&Bs[kr][c] = *(const float4*)bp;
        }
        __syncthreads();
#pragma unroll
        for (int kk = 0; kk < 16; kk++) {
            float4 a = *(const float4*)&As[kk][ty * 4];
            float4 bb0 = *(const float4*)&Bs[kk][tx * 8];
            float4 bb1 = *(const float4*)&Bs[kk][tx * 8 + 4];
            float av[4] = {a.x, a.y, a.z, a.w};
            float bv[8] = {bb0.x, bb0.y, bb0.z, bb0.w, bb1.x, bb1.y, bb1.z, bb1.w};
#pragma unroll
            for (int i = 0; i < 4; i++)
#pragma unroll
                for (int j = 0; j < 8; j++) acc[i][j] += av[i] * bv[j];
        }
        __syncthreads();
    }

    int c0 = tx * 8;
#pragma unroll
    for (int i = 0; i < 4; i++) {
        int m = bm + ty * 4 + i;
        if (m >= NN) break;
        float4 o0 = make_float4(acc[i][0], acc[i][1], acc[i][2], acc[i][3]);
        float4 o1 = make_float4(acc[i][4], acc[i][5], acc[i][6], acc[i][7]);
        *(float4*)&g_C[(size_t)m * 80 + c0] = o0;
        *(float4*)&g_C[(size_t)m * 80 + c0 + 4] = o1;
    }
}

// ---------------- layer-2 aggregation + epilogue ----------------
// out[n, :] = scatter-mean(A)[n, :] + R[n, :] + b2   (A = C[:, :40], R = C[:, 40:])
__global__ void k_final(const float* __restrict__ b2, float* __restrict__ out) {
    int gt = blockIdx.x * blockDim.x + threadIdx.x;
    int w = gt >> 5;
    int lane = gt & 31;
    if (w >= NN) return;
    int s0 = g_row[w], s1 = g_row[w + 1];
    if (lane < 20) {
        float2 acc = make_float2(0.f, 0.f);
        int i = s0;
        for (; i + 2 <= s1; i += 2) {
            int sa = g_src[i], sb = g_src[i + 1];
            float2 a = *(const float2*)&g_C[(size_t)sa * 80 + lane * 2];
            float2 b = *(const float2*)&g_C[(size_t)sb * 80 + lane * 2];
            acc.x += a.x; acc.y += a.y;
            acc.x += b.x; acc.y += b.y;
        }
        if (i < s1) {
            int sa = g_src[i];
            float2 a = *(const float2*)&g_C[(size_t)sa * 80 + lane * 2];
            acc.x += a.x; acc.y += a.y;
        }
        int cnt = s1 - s0; if (cnt < 1) cnt = 1;
        float sc = 1.0f / (float)cnt;
        float2 r = *(const float2*)&g_C[(size_t)w * 80 + 40 + lane * 2];
        float2 bb = *(const float2*)&b2[lane * 2];
        float2 o;
        o.x = acc.x * sc + r.x + bb.x;
        o.y = acc.y * sc + r.y + bb.y;
        *(float2*)&out[(size_t)w * 40 + lane * 2] = o;
    }
}

// ---------------- launcher ----------------
extern "C" void kernel_launch(void* const* d_in, const int* in_sizes, int n_in,
                              void* d_out, int out_size) {
    const float* x   = (const float*)d_in[0];
    const void*  ei  = d_in[1];
    const float* W1l = (const float*)d_in[2];
    const float* b1  = (const float*)d_in[3];
    const float* W1r = (const float*)d_in[4];
    const float* W2l = (const float*)d_in[5];
    const float* b2  = (const float*)d_in[6];
    const float* W2r = (const float*)d_in[7];
    float* out = (float*)d_out;

    k_detect<<<1, 256>>>((const int*)ei);
    k_zero<<<(NN + 255) / 256, 256>>>();
    k_hist<<<(NE + 255) / 256, 256>>>(ei);
    k_scan<<<1, 1024>>>();
    k_scatter<<<(NE + 255) / 256, 256>>>(ei);
    k_agg1<<<(NN + 7) / 8, 256>>>(x);                 // 8 warps/block, warp per node
    k_gemm1<<<(NN + 63) / 64, 256>>>(x, W1l, W1r, b1);
    k_gemm2<<<(NN + 63) / 64, 160>>>(W2l, W2r);
    k_final<<<(NN + 7) / 8, 256>>>(b2, out);
}

// round 4
// speedup vs baseline: 1.0605x; 1.0605x over previous
#include <cuda_runtime.h>

#define NN 50000
#define NE 800000
#define DIN 128
#define NC 40
#define NBLK 196   // (NN+255)/256

// ---- scratch (device globals; no allocation) ----
__device__ int   g_is64;
__device__ int   g_deg[NN];
__device__ int   g_row[NN + 1];
__device__ int   g_cur[NN];
__device__ int   g_src[NE];
__device__ int   g_part[256];
__device__ int   g_ppre[256];
__device__ float g_agg1[(size_t)NN * DIN];   // scatter-mean(x)
__device__ float g_h[(size_t)NN * DIN];      // relu(layer1)
__device__ float g_C[(size_t)NN * 80];       // [A | R] = h @ [W2_l | W2_r]

// ---------------- dtype detection for edge_index ----------------
__global__ void k_detect(const int* __restrict__ w) {
    __shared__ int any;
    if (threadIdx.x == 0) any = 0;
    __syncthreads();
    for (int i = threadIdx.x; i < 4096; i += blockDim.x) {
        if (w[2 * i + 1] != 0) any = 1;
    }
    __syncthreads();
    if (threadIdx.x == 0) g_is64 = (any == 0) ? 1 : 0;
}

__device__ __forceinline__ int load_idx(const void* eiv, long long pos) {
    int v;
    if (g_is64) v = (int)((const long long*)eiv)[pos];
    else        v = ((const int*)eiv)[pos];
    v = v < 0 ? 0 : (v >= NN ? NN - 1 : v);
    return v;
}

// ---------------- CSR build ----------------
__global__ void k_zero() {
    int i = blockIdx.x * blockDim.x + threadIdx.x;
    if (i < NN) g_deg[i] = 0;
}

__global__ void k_hist(const void* __restrict__ eiv) {
    int e = blockIdx.x * blockDim.x + threadIdx.x;
    if (e < NE) {
        int d = load_idx(eiv, (long long)NE + e);
        atomicAdd(&g_deg[d], 1);
    }
}

// phase 1: per-block sums of 256 degrees
__global__ void k_reduce() {
    __shared__ int s[256];
    int b = blockIdx.x, t = threadIdx.x;
    int i = b * 256 + t;
    s[t] = (i < NN) ? g_deg[i] : 0;
    __syncthreads();
    for (int off = 128; off > 0; off >>= 1) {
        if (t < off) s[t] += s[t + off];
        __syncthreads();
    }
    if (t == 0) g_part[b] = s[0];
}

// phase 2: single-block scan of 196 partials (tiny)
__global__ void k_scanpart() {
    __shared__ int s[256];
    int t = threadIdx.x;
    int v = (t < NBLK) ? g_part[t] : 0;
    s[t] = v;
    __syncthreads();
    for (int off = 1; off < 256; off <<= 1) {
        int u = (t >= off) ? s[t - off] : 0;
        __syncthreads();
        s[t] += u;
        __syncthreads();
    }
    if (t < NBLK) g_ppre[t] = (t == 0) ? 0 : s[t - 1];
    if (t == 255) g_row[NN] = s[255];
}

// phase 3: per-block exclusive scan + global offset
__global__ void k_scanblk() {
    __shared__ int s[256];
    int b = blockIdx.x, t = threadIdx.x;
    int i = b * 256 + t;
    int d = (i < NN) ? g_deg[i] : 0;
    s[t] = d;
    __syncthreads();
    for (int off = 1; off < 256; off <<= 1) {
        int u = (t >= off) ? s[t - off] : 0;
        __syncthreads();
        s[t] += u;
        __syncthreads();
    }
    int excl = s[t] - d + g_ppre[b];
    if (i < NN) { g_row[i] = excl; g_cur[i] = excl; }
}

__global__ void k_scatter(const void* __restrict__ eiv) {
    int e = blockIdx.x * blockDim.x + threadIdx.x;
    if (e < NE) {
        int srcv = load_idx(eiv, e);
        int d    = load_idx(eiv, (long long)NE + e);
        int pos = atomicAdd(&g_cur[d], 1);
        g_src[pos] = srcv;
    }
}

// ---------------- layer-1 aggregation: agg1 = scatter-mean(x) ----------------
__global__ void k_agg1(const float* __restrict__ x) {
    int gt = blockIdx.x * blockDim.x + threadIdx.x;
    int w = gt >> 5;
    int lane = gt & 31;
    if (w >= NN) return;
    int s0 = g_row[w], s1 = g_row[w + 1];
    const float4* X = (const float4*)x;
    float4 acc = make_float4(0.f, 0.f, 0.f, 0.f);
    int i = s0;
    for (; i + 2 <= s1; i += 2) {
        int sa = g_src[i], sb = g_src[i + 1];
        float4 a = X[(size_t)sa * 32 + lane];
        float4 b = X[(size_t)sb * 32 + lane];
        acc.x += a.x; acc.y += a.y; acc.z += a.z; acc.w += a.w;
        acc.x += b.x; acc.y += b.y; acc.z += b.z; acc.w += b.w;
    }
    if (i < s1) {
        int sa = g_src[i];
        float4 a = X[(size_t)sa * 32 + lane];
        acc.x += a.x; acc.y += a.y; acc.z += a.z; acc.w += a.w;
    }
    int cnt = s1 - s0; if (cnt < 1) cnt = 1;
    float sc = 1.0f / (float)cnt;
    float4 o = make_float4(acc.x * sc, acc.y * sc, acc.z * sc, acc.w * sc);
    ((float4*)g_agg1)[(size_t)w * 32 + lane] = o;
}

// ---------------- GEMM1: h = relu([agg1 | x] @ [W1_l ; W1_r] + b1) ----------------
// BM=128, BN=128, BK=16, 256 threads, thread tile 8x8
__global__ __launch_bounds__(256) void k_gemm1(const float* __restrict__ x,
                                               const float* __restrict__ W1l,
                                               const float* __restrict__ W1r,
                                               const float* __restrict__ b1) {
    __shared__ float As[16][128];
    __shared__ float Bs[16][128];
    int t = threadIdx.x;
    int bm = blockIdx.x * 128;
    int ty = t >> 4;        // 0..15
    int tx = t & 15;        // 0..15

    float acc[8][8];
#pragma unroll
    for (int i = 0; i < 8; i++)
#pragma unroll
        for (int j = 0; j < 8; j++) acc[i][j] = 0.f;

    for (int k0 = 0; k0 < 256; k0 += 16) {
        // A tile (128 x 16), k-major in smem; 512 float4 slots, 2 per thread
#pragma unroll
        for (int r = 0; r < 2; r++) {
            int s = t + r * 256;
            int row = s >> 2, q = s & 3;
            int m = bm + row; if (m >= NN) m = NN - 1;
            int kg = k0 + q * 4;
            const float* ap = (kg < 128) ? (g_agg1 + (size_t)m * 128 + kg)
                                         : (x + (size_t)m * 128 + (kg - 128));
            float4 av = *(const float4*)ap;
            As[q * 4 + 0][row] = av.x;
            As[q * 4 + 1][row] = av.y;
            As[q * 4 + 2][row] = av.z;
            As[q * 4 + 3][row] = av.w;
        }
        // B tile (16 x 128); 512 float4 slots, 2 per thread
#pragma unroll
        for (int r = 0; r < 2; r++) {
            int s = t + r * 256;
            int kr = s >> 5;
            int c = (s & 31) * 4;
            int kg = k0 + kr;
            const float* bp = (kg < 128) ? (W1l + (size_t)kg * 128 + c)
                                         : (W1r + (size_t)(kg - 128) * 128 + c);
            *(float4*)&Bs[kr][c] = *(const float4*)bp;
        }
        __syncthreads();
#pragma unroll
        for (int kk = 0; kk < 16; kk++) {
            float4 a0 = *(const float4*)&As[kk][ty * 8];
            float4 a1 = *(const float4*)&As[kk][ty * 8 + 4];
            float4 b0 = *(const float4*)&Bs[kk][tx * 8];
            float4 b1v = *(const float4*)&Bs[kk][tx * 8 + 4];
            float av[8] = {a0.x, a0.y, a0.z, a0.w, a1.x, a1.y, a1.z, a1.w};
            float bv[8] = {b0.x, b0.y, b0.z, b0.w, b1v.x, b1v.y, b1v.z, b1v.w};
#pragma unroll
            for (int i = 0; i < 8; i++)
#pragma unroll
                for (int j = 0; j < 8; j++) acc[i][j] += av[i] * bv[j];
        }
        __syncthreads();
    }

    int c0 = tx * 8;
    float bias[8];
#pragma unroll
    for (int j = 0; j < 8; j++) bias[j] = b1[c0 + j];
#pragma unroll
    for (int i = 0; i < 8; i++) {
        int m = bm + ty * 8 + i;
        if (m >= NN) break;
        float4 o0, o1;
        o0.x = fmaxf(acc[i][0] + bias[0], 0.f);
        o0.y = fmaxf(acc[i][1] + bias[1], 0.f);
        o0.z = fmaxf(acc[i][2] + bias[2], 0.f);
        o0.w = fmaxf(acc[i][3] + bias[3], 0.f);
        o1.x = fmaxf(acc[i][4] + bias[4], 0.f);
        o1.y = fmaxf(acc[i][5] + bias[5], 0.f);
        o1.z = fmaxf(acc[i][6] + bias[6], 0.f);
        o1.w = fmaxf(acc[i][7] + bias[7], 0.f);
        *(float4*)&g_h[(size_t)m * 128 + c0] = o0;
        *(float4*)&g_h[(size_t)m * 128 + c0 + 4] = o1;
    }
}

// ---------------- GEMM2: C = h @ [W2_l | W2_r]  ([50k,128]@[128,80]) ----------------
// BM=128, BN=80, BK=16, 160 threads, thread tile 8x8
__global__ __launch_bounds__(160) void k_gemm2(const float* __restrict__ W2l,
                                               const float* __restrict__ W2r) {
    __shared__ float As[16][128];
    __shared__ float Bs[16][80];
    int t = threadIdx.x;
    int bm = blockIdx.x * 128;
    int ty = t / 10;        // 0..15
    int tx = t % 10;        // 0..9

    float acc[8][8];
#pragma unroll
    for (int i = 0; i < 8; i++)
#pragma unroll
        for (int j = 0; j < 8; j++) acc[i][j] = 0.f;

    for (int k0 = 0; k0 < 128; k0 += 16) {
        // A tile: 128 rows x 16 k = 512 float4-slots
        for (int s = t; s < 512; s += 160) {
            int row = s >> 2, q = s & 3;
            int m = bm + row; if (m >= NN) m = NN - 1;
            int kg = k0 + q * 4;
            float4 av = *(const float4*)(g_h + (size_t)m * 128 + kg);
            As[q * 4 + 0][row] = av.x;
            As[q * 4 + 1][row] = av.y;
            As[q * 4 + 2][row] = av.z;
            As[q * 4 + 3][row] = av.w;
        }
        // B tile: 16 k x 80 cols = 320 float4-slots
        for (int s = t; s < 320; s += 160) {
            int kr = s / 20;
            int c = (s % 20) * 4;
            int kg = k0 + kr;
            const float* bp = (c < 40) ? (W2l + (size_t)kg * 40 + c)
                                       : (W2r + (size_t)kg * 40 + (c - 40));
            *(float4*)&Bs[kr][c] = *(const float4*)bp;
        }
        __syncthreads();
#pragma unroll
        for (int kk = 0; kk < 16; kk++) {
            float4 a0 = *(const float4*)&As[kk][ty * 8];
            float4 a1 = *(const float4*)&As[kk][ty * 8 + 4];
            float4 b0 = *(const float4*)&Bs[kk][tx * 8];
            float4 b1v = *(const float4*)&Bs[kk][tx * 8 + 4];
            float av[8] = {a0.x, a0.y, a0.z, a0.w, a1.x, a1.y, a1.z, a1.w};
            float bv[8] = {b0.x, b0.y, b0.z, b0.w, b1v.x, b1v.y, b1v.z, b1v.w};
#pragma unroll
            for (int i = 0; i < 8; i++)
#pragma unroll
                for (int j = 0; j < 8; j++) acc[i][j] += av[i] * bv[j];
        }
        __syncthreads();
    }

    int c0 = tx * 8;
#pragma unroll
    for (int i = 0; i < 8; i++) {
        int m = bm + ty * 8 + i;
        if (m >= NN) break;
        float4 o0 = make_float4(acc[i][0], acc[i][1], acc[i][2], acc[i][3]);
        float4 o1 = make_float4(acc[i][4], acc[i][5], acc[i][6], acc[i][7]);
        *(float4*)&g_C[(size_t)m * 80 + c0] = o0;
        *(float4*)&g_C[(size_t)m * 80 + c0 + 4] = o1;
    }
}

// ---------------- layer-2 aggregation + epilogue ----------------
__global__ void k_final(const float* __restrict__ b2, float* __restrict__ out) {
    int gt = blockIdx.x * blockDim.x + threadIdx.x;
    int w = gt >> 5;
    int lane = gt & 31;
    if (w >= NN) return;
    int s0 = g_row[w], s1 = g_row[w + 1];
    if (lane < 20) {
        float2 acc = make_float2(0.f, 0.f);
        int i = s0;
        for (; i + 2 <= s1; i += 2) {
            int sa = g_src[i], sb = g_src[i + 1];
            float2 a = *(const float2*)&g_C[(size_t)sa * 80 + lane * 2];
            float2 b = *(const float2*)&g_C[(size_t)sb * 80 + lane * 2];
            acc.x += a.x; acc.y += a.y;
            acc.x += b.x; acc.y += b.y;
        }
        if (i < s1) {
            int sa = g_src[i];
            float2 a = *(const float2*)&g_C[(size_t)sa * 80 + lane * 2];
            acc.x += a.x; acc.y += a.y;
        }
        int cnt = s1 - s0; if (cnt < 1) cnt = 1;
        float sc = 1.0f / (float)cnt;
        float2 r = *(const float2*)&g_C[(size_t)w * 80 + 40 + lane * 2];
        float2 bb = *(const float2*)&b2[lane * 2];
        float2 o;
        o.x = acc.x * sc + r.x + bb.x;
        o.y = acc.y * sc + r.y + bb.y;
        *(float2*)&out[(size_t)w * 40 + lane * 2] = o;
    }
}

// ---------------- launcher ----------------
extern "C" void kernel_launch(void* const* d_in, const int* in_sizes, int n_in,
                              void* d_out, int out_size) {
    const float* x   = (const float*)d_in[0];
    const void*  ei  = d_in[1];
    const float* W1l = (const float*)d_in[2];
    const float* b1  = (const float*)d_in[3];
    const float* W1r = (const float*)d_in[4];
    const float* W2l = (const float*)d_in[5];
    const float* b2  = (const float*)d_in[6];
    const float* W2r = (const float*)d_in[7];
    float* out = (float*)d_out;

    k_detect<<<1, 256>>>((const int*)ei);
    k_zero<<<NBLK, 256>>>();
    k_hist<<<(NE + 255) / 256, 256>>>(ei);
    k_reduce<<<NBLK, 256>>>();
    k_scanpart<<<1, 256>>>();
    k_scanblk<<<NBLK, 256>>>();
    k_scatter<<<(NE + 255) / 256, 256>>>(ei);
    k_agg1<<<(NN + 7) / 8, 256>>>(x);
    k_gemm1<<<(NN + 127) / 128, 256>>>(x, W1l, W1r, b1);
    k_gemm2<<<(NN + 127) / 128, 160>>>(W2l, W2r);
    k_final<<<(NN + 7) / 8, 256>>>(b2, out);
}

// round 6
// speedup vs baseline: 1.7473x; 1.6476x over previous
#include <cuda_runtime.h>
#include <cstdint>

#define NN 50000
#define NE 800000
#define DIN 128
#define NC 40
#define NBLK 196   // (NN+255)/256

// ---- scratch (device globals; no allocation) ----
__device__ int   g_is64;
__device__ int   g_deg[NN];
__device__ int   g_row[NN + 1];
__device__ int   g_cur[NN];
__device__ int   g_src[NE];
__device__ int   g_part[256];
__device__ int   g_ppre[256];
__device__ float g_agg1[(size_t)NN * DIN];   // scatter-mean(x)
__device__ float g_h[(size_t)NN * DIN];      // relu(layer1)
__device__ float g_C[(size_t)NN * 80];       // [A | R] = h @ [W2_l | W2_r]

// ---------------- dtype detection for edge_index ----------------
__global__ void k_detect(const int* __restrict__ w) {
    __shared__ int any;
    if (threadIdx.x == 0) any = 0;
    __syncthreads();
    for (int i = threadIdx.x; i < 4096; i += blockDim.x) {
        if (w[2 * i + 1] != 0) any = 1;
    }
    __syncthreads();
    if (threadIdx.x == 0) g_is64 = (any == 0) ? 1 : 0;
}

__device__ __forceinline__ int load_idx(const void* eiv, long long pos) {
    int v;
    if (g_is64) v = (int)((const long long*)eiv)[pos];
    else        v = ((const int*)eiv)[pos];
    v = v < 0 ? 0 : (v >= NN ? NN - 1 : v);
    return v;
}

// ---------------- CSR build ----------------
__global__ void k_zero() {
    int i = blockIdx.x * blockDim.x + threadIdx.x;
    if (i < NN) g_deg[i] = 0;
}

__global__ void k_hist(const void* __restrict__ eiv) {
    int e = blockIdx.x * blockDim.x + threadIdx.x;
    if (e < NE) {
        int d = load_idx(eiv, (long long)NE + e);
        atomicAdd(&g_deg[d], 1);
    }
}

__global__ void k_reduce() {
    __shared__ int s[256];
    int b = blockIdx.x, t = threadIdx.x;
    int i = b * 256 + t;
    s[t] = (i < NN) ? g_deg[i] : 0;
    __syncthreads();
    for (int off = 128; off > 0; off >>= 1) {
        if (t < off) s[t] += s[t + off];
        __syncthreads();
    }
    if (t == 0) g_part[b] = s[0];
}

__global__ void k_scanpart() {
    __shared__ int s[256];
    int t = threadIdx.x;
    int v = (t < NBLK) ? g_part[t] : 0;
    s[t] = v;
    __syncthreads();
    for (int off = 1; off < 256; off <<= 1) {
        int u = (t >= off) ? s[t - off] : 0;
        __syncthreads();
        s[t] += u;
        __syncthreads();
    }
    if (t < NBLK) g_ppre[t] = (t == 0) ? 0 : s[t - 1];
    if (t == 255) g_row[NN] = s[255];
}

__global__ void k_scanblk() {
    __shared__ int s[256];
    int b = blockIdx.x, t = threadIdx.x;
    int i = b * 256 + t;
    int d = (i < NN) ? g_deg[i] : 0;
    s[t] = d;
    __syncthreads();
    for (int off = 1; off < 256; off <<= 1) {
        int u = (t >= off) ? s[t - off] : 0;
        __syncthreads();
        s[t] += u;
        __syncthreads();
    }
    int excl = s[t] - d + g_ppre[b];
    if (i < NN) { g_row[i] = excl; g_cur[i] = excl; }
}

__global__ void k_scatter(const void* __restrict__ eiv) {
    int e = blockIdx.x * blockDim.x + threadIdx.x;
    if (e < NE) {
        int srcv = load_idx(eiv, e);
        int d    = load_idx(eiv, (long long)NE + e);
        int pos = atomicAdd(&g_cur[d], 1);
        g_src[pos] = srcv;
    }
}

// ---------------- layer-1 aggregation ----------------
__global__ void k_agg1(const float* __restrict__ x) {
    int gt = blockIdx.x * blockDim.x + threadIdx.x;
    int w = gt >> 5;
    int lane = gt & 31;
    if (w >= NN) return;
    int s0 = g_row[w], s1 = g_row[w + 1];
    const float4* X = (const float4*)x;
    float4 acc = make_float4(0.f, 0.f, 0.f, 0.f);
    int i = s0;
    for (; i + 2 <= s1; i += 2) {
        int sa = g_src[i], sb = g_src[i + 1];
        float4 a = X[(size_t)sa * 32 + lane];
        float4 b = X[(size_t)sb * 32 + lane];
        acc.x += a.x; acc.y += a.y; acc.z += a.z; acc.w += a.w;
        acc.x += b.x; acc.y += b.y; acc.z += b.z; acc.w += b.w;
    }
    if (i < s1) {
        int sa = g_src[i];
        float4 a = X[(size_t)sa * 32 + lane];
        acc.x += a.x; acc.y += a.y; acc.z += a.z; acc.w += a.w;
    }
    int cnt = s1 - s0; if (cnt < 1) cnt = 1;
    float sc = 1.0f / (float)cnt;
    float4 o = make_float4(acc.x * sc, acc.y * sc, acc.z * sc, acc.w * sc);
    ((float4*)g_agg1)[(size_t)w * 32 + lane] = o;
}

// ---------------- tf32 helpers ----------------
__device__ __forceinline__ void mma_tf32(float* d, const uint32_t* a, uint32_t b0, uint32_t b1) {
    asm volatile(
        "mma.sync.aligned.m16n8k8.row.col.f32.tf32.tf32.f32 "
        "{%0,%1,%2,%3}, {%4,%5,%6,%7}, {%8,%9}, {%0,%1,%2,%3};\n"
        : "+f"(d[0]), "+f"(d[1]), "+f"(d[2]), "+f"(d[3])
        : "r"(a[0]), "r"(a[1]), "r"(a[2]), "r"(a[3]), "r"(b0), "r"(b1));
}

// split v into tf32 hi + tf32 lo (error compensation: hi+lo ~ 21 mantissa bits)
__device__ __forceinline__ void split_tf32(float v, uint32_t& hi, uint32_t& lo) {
    float h;
    asm("cvt.rna.tf32.f32 %0, %1;\n" : "=f"(h) : "f"(v));
    float l = v - h;
    float l32;
    asm("cvt.rna.tf32.f32 %0, %1;\n" : "=f"(l32) : "f"(l));
    hi = __float_as_uint(h);
    lo = __float_as_uint(l32);
}

// ---------------- GEMM1: h = relu([agg1 | x] @ [W1_l ; W1_r] + b1) ----------------
// BM=128, BN=128, BK=32, 256 threads. Warp grid 4x2 (m x n), warp tile 32x64.
// 3xTF32 compensated: d += Ahi*Bhi + Alo*Bhi + Ahi*Blo
__global__ __launch_bounds__(256) void k_gemm1(const float* __restrict__ x,
                                               const float* __restrict__ W1l,
                                               const float* __restrict__ W1r,
                                               const float* __restrict__ b1) {
    __shared__ float As[128][36];
    __shared__ float Bs[32][132];
    int t = threadIdx.x;
    int warp = t >> 5, lane = t & 31;
    int gid = lane >> 2, tig = lane & 3;
    int wm = warp >> 1, wn = warp & 1;
    int bm = blockIdx.x * 128;

    float d[2][8][4];
#pragma unroll
    for (int mt = 0; mt < 2; mt++)
#pragma unroll
        for (int nt = 0; nt < 8; nt++)
#pragma unroll
            for (int q = 0; q < 4; q++) d[mt][nt][q] = 0.f;

    for (int k0 = 0; k0 < 256; k0 += 32) {
#pragma unroll
        for (int r = 0; r < 4; r++) {
            int s = r * 256 + t;
            int row = s >> 3, q = s & 7;
            int m = bm + row; if (m >= NN) m = NN - 1;
            int kg = k0 + q * 4;
            const float* ap = (kg < 128) ? (g_agg1 + (size_t)m * 128 + kg)
                                         : (x + (size_t)m * 128 + (kg - 128));
            *(float4*)&As[row][q * 4] = *(const float4*)ap;
        }
#pragma unroll
        for (int r = 0; r < 4; r++) {
            int s = r * 256 + t;
            int kr = s >> 5, c = (s & 31) * 4;
            int kg = k0 + kr;
            const float* bp = (kg < 128) ? (W1l + (size_t)kg * 128 + c)
                                         : (W1r + (size_t)(kg - 128) * 128 + c);
            *(float4*)&Bs[kr][c] = *(const float4*)bp;
        }
        __syncthreads();
#pragma unroll
        for (int ks = 0; ks < 4; ks++) {
            int kb = ks * 8;
            uint32_t ahi[2][4], alo[2][4];
#pragma unroll
            for (int mt = 0; mt < 2; mt++) {
                int rb = wm * 32 + mt * 16;
                split_tf32(As[rb + gid][kb + tig],     ahi[mt][0], alo[mt][0]);
                split_tf32(As[rb + gid + 8][kb + tig], ahi[mt][1], alo[mt][1]);
                split_tf32(As[rb + gid][kb + tig + 4],     ahi[mt][2], alo[mt][2]);
                split_tf32(As[rb + gid + 8][kb + tig + 4], ahi[mt][3], alo[mt][3]);
            }
#pragma unroll
            for (int nt = 0; nt < 8; nt++) {
                int cb = wn * 64 + nt * 8;
                uint32_t b0h, b0l, b1h, b1l;
                split_tf32(Bs[kb + tig][cb + gid],     b0h, b0l);
                split_tf32(Bs[kb + tig + 4][cb + gid], b1h, b1l);
#pragma unroll
                for (int mt = 0; mt < 2; mt++) {
                    mma_tf32(d[mt][nt], ahi[mt], b0h, b1h);
                    mma_tf32(d[mt][nt], alo[mt], b0h, b1h);
                    mma_tf32(d[mt][nt], ahi[mt], b0l, b1l);
                }
            }
        }
        __syncthreads();
    }

#pragma unroll
    for (int mt = 0; mt < 2; mt++) {
        int r0 = bm + wm * 32 + mt * 16 + gid;
#pragma unroll
        for (int nt = 0; nt < 8; nt++) {
            int col = wn * 64 + nt * 8 + 2 * tig;
            float bb0 = b1[col], bb1 = b1[col + 1];
            if (r0 < NN) {
                float2 o;
                o.x = fmaxf(d[mt][nt][0] + bb0, 0.f);
                o.y = fmaxf(d[mt][nt][1] + bb1, 0.f);
                *(float2*)&g_h[(size_t)r0 * 128 + col] = o;
            }
            if (r0 + 8 < NN) {
                float2 o;
                o.x = fmaxf(d[mt][nt][2] + bb0, 0.f);
                o.y = fmaxf(d[mt][nt][3] + bb1, 0.f);
                *(float2*)&g_h[(size_t)(r0 + 8) * 128 + col] = o;
            }
        }
    }
}

// ---------------- GEMM2: C = h @ [W2_l | W2_r]  ([50k,128]@[128,80]) ----------------
__global__ __launch_bounds__(256) void k_gemm2(const float* __restrict__ W2l,
                                               const float* __restrict__ W2r) {
    __shared__ float As[128][36];
    __shared__ float Bs[32][88];
    int t = threadIdx.x;
    int warp = t >> 5, lane = t & 31;
    int gid = lane >> 2, tig = lane & 3;
    int wm = warp >> 1, wn = warp & 1;
    int bm = blockIdx.x * 128;

    float d[2][5][4];
#pragma unroll
    for (int mt = 0; mt < 2; mt++)
#pragma unroll
        for (int nt = 0; nt < 5; nt++)
#pragma unroll
            for (int q = 0; q < 4; q++) d[mt][nt][q] = 0.f;

    for (int k0 = 0; k0 < 128; k0 += 32) {
#pragma unroll
        for (int r = 0; r < 4; r++) {
            int s = r * 256 + t;
            int row = s >> 3, q = s & 7;
            int m = bm + row; if (m >= NN) m = NN - 1;
            int kg = k0 + q * 4;
            *(float4*)&As[row][q * 4] = *(const float4*)(g_h + (size_t)m * 128 + kg);
        }
        for (int s = t; s < 640; s += 256) {
            int kr = s / 20, c = (s % 20) * 4;
            int kg = k0 + kr;
            const float* bp = (c < 40) ? (W2l + (size_t)kg * 40 + c)
                                       : (W2r + (size_t)kg * 40 + (c - 40));
            *(float4*)&Bs[kr][c] = *(const float4*)bp;
        }
        __syncthreads();
#pragma unroll
        for (int ks = 0; ks < 4; ks++) {
            int kb = ks * 8;
            uint32_t ahi[2][4], alo[2][4];
#pragma unroll
            for (int mt = 0; mt < 2; mt++) {
                int rb = wm * 32 + mt * 16;
                split_tf32(As[rb + gid][kb + tig],     ahi[mt][0], alo[mt][0]);
                split_tf32(As[rb + gid + 8][kb + tig], ahi[mt][1], alo[mt][1]);
                split_tf32(As[rb + gid][kb + tig + 4],     ahi[mt][2], alo[mt][2]);
                split_tf32(As[rb + gid + 8][kb + tig + 4], ahi[mt][3], alo[mt][3]);
            }
#pragma unroll
            for (int nt = 0; nt < 5; nt++) {
                int cb = wn * 40 + nt * 8;
                uint32_t b0h, b0l, b1h, b1l;
                split_tf32(Bs[kb + tig][cb + gid],     b0h, b0l);
                split_tf32(Bs[kb + tig + 4][cb + gid], b1h, b1l);
#pragma unroll
                for (int mt = 0; mt < 2; mt++) {
                    mma_tf32(d[mt][nt], ahi[mt], b0h, b1h);
                    mma_tf32(d[mt][nt], alo[mt], b0h, b1h);
                    mma_tf32(d[mt][nt], ahi[mt], b0l, b1l);
                }
            }
        }
        __syncthreads();
    }

#pragma unroll
    for (int mt = 0; mt < 2; mt++) {
        int r0 = bm + wm * 32 + mt * 16 + gid;
#pragma unroll
        for (int nt = 0; nt < 5; nt++) {
            int col = wn * 40 + nt * 8 + 2 * tig;
            if (r0 < NN) {
                float2 o = make_float2(d[mt][nt][0], d[mt][nt][1]);
                *(float2*)&g_C[(size_t)r0 * 80 + col] = o;
            }
            if (r0 + 8 < NN) {
                float2 o = make_float2(d[mt][nt][2], d[mt][nt][3]);
                *(float2*)&g_C[(size_t)(r0 + 8) * 80 + col] = o;
            }
        }
    }
}

// ---------------- layer-2 aggregation + epilogue ----------------
__global__ void k_final(const float* __restrict__ b2, float* __restrict__ out) {
    int gt = blockIdx.x * blockDim.x + threadIdx.x;
    int w = gt >> 5;
    int lane = gt & 31;
    if (w >= NN) return;
    int s0 = g_row[w], s1 = g_row[w + 1];
    if (lane < 20) {
        float2 acc = make_float2(0.f, 0.f);
        int i = s0;
        for (; i + 2 <= s1; i += 2) {
            int sa = g_src[i], sb = g_src[i + 1];
            float2 a = *(const float2*)&g_C[(size_t)sa * 80 + lane * 2];
            float2 b = *(const float2*)&g_C[(size_t)sb * 80 + lane * 2];
            acc.x += a.x; acc.y += a.y;
            acc.x += b.x; acc.y += b.y;
        }
        if (i < s1) {
            int sa = g_src[i];
            float2 a = *(const float2*)&g_C[(size_t)sa * 80 + lane * 2];
            acc.x += a.x; acc.y += a.y;
        }
        int cnt = s1 - s0; if (cnt < 1) cnt = 1;
        float sc = 1.0f / (float)cnt;
        float2 r = *(const float2*)&g_C[(size_t)w * 80 + 40 + lane * 2];
        float2 bb = *(const float2*)&b2[lane * 2];
        float2 o;
        o.x = acc.x * sc + r.x + bb.x;
        o.y = acc.y * sc + r.y + bb.y;
        *(float2*)&out[(size_t)w * 40 + lane * 2] = o;
    }
}

// ---------------- launcher ----------------
extern "C" void kernel_launch(void* const* d_in, const int* in_sizes, int n_in,
                              void* d_out, int out_size) {
    const float* x   = (const float*)d_in[0];
    const void*  ei  = d_in[1];
    const float* W1l = (const float*)d_in[2];
    const float* b1  = (const float*)d_in[3];
    const float* W1r = (const float*)d_in[4];
    const float* W2l = (const float*)d_in[5];
    const float* b2  = (const float*)d_in[6];
    const float* W2r = (const float*)d_in[7];
    float* out = (float*)d_out;

    k_detect<<<1, 256>>>((const int*)ei);
    k_zero<<<NBLK, 256>>>();
    k_hist<<<(NE + 255) / 256, 256>>>(ei);
    k_reduce<<<NBLK, 256>>>();
    k_scanpart<<<1, 256>>>();
    k_scanblk<<<NBLK, 256>>>();
    k_scatter<<<(NE + 255) / 256, 256>>>(ei);
    k_agg1<<<(NN + 7) / 8, 256>>>(x);
    k_gemm1<<<(NN + 127) / 128, 256>>>(x, W1l, W1r, b1);
    k_gemm2<<<(NN + 127) / 128, 256>>>(W2l, W2r);
    k_final<<<(NN + 7) / 8, 256>>>(b2, out);
}

// round 7
// speedup vs baseline: 2.0119x; 1.1515x over previous
#include <cuda_runtime.h>
#include <cstdint>

#define NN 50000
#define NE 800000
#define DIN 128
#define NC 40
#define NBLK 196   // (NN+255)/256

// ---- scratch (device globals; no allocation) ----
__device__ int   g_is64;
__device__ int   g_deg[NN];
__device__ int   g_row[NN + 1];
__device__ int   g_cur[NN];
__device__ int   g_src[NE];
__device__ int   g_part[256];
__device__ int   g_ppre[256];
__device__ float g_agg1[(size_t)NN * DIN];   // scatter-mean(x)
__device__ float g_h[(size_t)NN * DIN];      // relu(layer1)
__device__ float g_C[(size_t)NN * 80];       // [A | R] = h @ [W2_l | W2_r]

// ---------------- zero + dtype detection (merged) ----------------
__global__ void k_zero_detect(const int* __restrict__ w) {
    int i = blockIdx.x * blockDim.x + threadIdx.x;
    if (i < NN) g_deg[i] = 0;
    if (blockIdx.x == 0) {
        __shared__ int any;
        if (threadIdx.x == 0) any = 0;
        __syncthreads();
        for (int j = threadIdx.x; j < 4096; j += blockDim.x) {
            if (w[2 * j + 1] != 0) any = 1;
        }
        __syncthreads();
        if (threadIdx.x == 0) g_is64 = (any == 0) ? 1 : 0;
    }
}

__device__ __forceinline__ int load_idx(const void* eiv, long long pos) {
    int v;
    if (g_is64) v = (int)((const long long*)eiv)[pos];
    else        v = ((const int*)eiv)[pos];
    v = v < 0 ? 0 : (v >= NN ? NN - 1 : v);
    return v;
}

// ---------------- CSR build ----------------
__global__ void k_hist(const void* __restrict__ eiv) {
    int e = blockIdx.x * blockDim.x + threadIdx.x;
    if (e < NE) {
        int d = load_idx(eiv, (long long)NE + e);
        atomicAdd(&g_deg[d], 1);
    }
}

__global__ void k_reduce() {
    __shared__ int s[256];
    int b = blockIdx.x, t = threadIdx.x;
    int i = b * 256 + t;
    s[t] = (i < NN) ? g_deg[i] : 0;
    __syncthreads();
    for (int off = 128; off > 0; off >>= 1) {
        if (t < off) s[t] += s[t + off];
        __syncthreads();
    }
    if (t == 0) g_part[b] = s[0];
}

__global__ void k_scanpart() {
    __shared__ int s[256];
    int t = threadIdx.x;
    int v = (t < NBLK) ? g_part[t] : 0;
    s[t] = v;
    __syncthreads();
    for (int off = 1; off < 256; off <<= 1) {
        int u = (t >= off) ? s[t - off] : 0;
        __syncthreads();
        s[t] += u;
        __syncthreads();
    }
    if (t < NBLK) g_ppre[t] = (t == 0) ? 0 : s[t - 1];
    if (t == 255) g_row[NN] = s[255];
}

__global__ void k_scanblk() {
    __shared__ int s[256];
    int b = blockIdx.x, t = threadIdx.x;
    int i = b * 256 + t;
    int d = (i < NN) ? g_deg[i] : 0;
    s[t] = d;
    __syncthreads();
    for (int off = 1; off < 256; off <<= 1) {
        int u = (t >= off) ? s[t - off] : 0;
        __syncthreads();
        s[t] += u;
        __syncthreads();
    }
    int excl = s[t] - d + g_ppre[b];
    if (i < NN) { g_row[i] = excl; g_cur[i] = excl; }
}

__global__ void k_scatter(const void* __restrict__ eiv) {
    int e = blockIdx.x * blockDim.x + threadIdx.x;
    if (e < NE) {
        int srcv = load_idx(eiv, e);
        int d    = load_idx(eiv, (long long)NE + e);
        int pos = atomicAdd(&g_cur[d], 1);
        g_src[pos] = srcv;
    }
}

// ---------------- layer-1 aggregation ----------------
__global__ void k_agg1(const float* __restrict__ x) {
    int gt = blockIdx.x * blockDim.x + threadIdx.x;
    int w = gt >> 5;
    int lane = gt & 31;
    if (w >= NN) return;
    int s0 = g_row[w], s1 = g_row[w + 1];
    const float4* X = (const float4*)x;
    float4 acc = make_float4(0.f, 0.f, 0.f, 0.f);
    int i = s0;
    for (; i + 4 <= s1; i += 4) {
        int sa = g_src[i], sb = g_src[i + 1], sc = g_src[i + 2], sd = g_src[i + 3];
        float4 a = X[(size_t)sa * 32 + lane];
        float4 b = X[(size_t)sb * 32 + lane];
        float4 c = X[(size_t)sc * 32 + lane];
        float4 e = X[(size_t)sd * 32 + lane];
        acc.x += a.x + b.x + c.x + e.x;
        acc.y += a.y + b.y + c.y + e.y;
        acc.z += a.z + b.z + c.z + e.z;
        acc.w += a.w + b.w + c.w + e.w;
    }
    for (; i < s1; i++) {
        int sa = g_src[i];
        float4 a = X[(size_t)sa * 32 + lane];
        acc.x += a.x; acc.y += a.y; acc.z += a.z; acc.w += a.w;
    }
    int cnt = s1 - s0; if (cnt < 1) cnt = 1;
    float sc = 1.0f / (float)cnt;
    float4 o = make_float4(acc.x * sc, acc.y * sc, acc.z * sc, acc.w * sc);
    ((float4*)g_agg1)[(size_t)w * 32 + lane] = o;
}

// ---------------- tf32 helpers ----------------
__device__ __forceinline__ void mma_tf32(float* d, const uint32_t* a, uint32_t b0, uint32_t b1) {
    asm volatile(
        "mma.sync.aligned.m16n8k8.row.col.f32.tf32.tf32.f32 "
        "{%0,%1,%2,%3}, {%4,%5,%6,%7}, {%8,%9}, {%0,%1,%2,%3};\n"
        : "+f"(d[0]), "+f"(d[1]), "+f"(d[2]), "+f"(d[3])
        : "r"(a[0]), "r"(a[1]), "r"(a[2]), "r"(a[3]), "r"(b0), "r"(b1));
}

// exact truncation split: hi = v with low 13 mantissa bits zeroed, lo = v - hi (exact).
// mma's tf32 operand truncation then loses only ~2^-21-relative info. 2 fast-pipe ops.
__device__ __forceinline__ void split_tf32(float v, uint32_t& hi, uint32_t& lo) {
    uint32_t u = __float_as_uint(v) & 0xFFFFE000u;
    hi = u;
    lo = __float_as_uint(v - __uint_as_float(u));
}

// ---------------- GEMM1: h = relu([agg1 | x] @ [W1_l ; W1_r] + b1) ----------------
// BM=128, BN=128, BK=32, 256 threads. Warp grid 4x2 (m x n), warp tile 32x64.
// 3xTF32 compensated: d += Ahi*Bhi + Alo*Bhi + Ahi*Blo
__global__ __launch_bounds__(256) void k_gemm1(const float* __restrict__ x,
                                               const float* __restrict__ W1l,
                                               const float* __restrict__ W1r,
                                               const float* __restrict__ b1) {
    __shared__ float As[128][36];
    __shared__ float Bs[32][132];
    int t = threadIdx.x;
    int warp = t >> 5, lane = t & 31;
    int gid = lane >> 2, tig = lane & 3;
    int wm = warp >> 1, wn = warp & 1;
    int bm = blockIdx.x * 128;

    float d[2][8][4];
#pragma unroll
    for (int mt = 0; mt < 2; mt++)
#pragma unroll
        for (int nt = 0; nt < 8; nt++)
#pragma unroll
            for (int q = 0; q < 4; q++) d[mt][nt][q] = 0.f;

    for (int k0 = 0; k0 < 256; k0 += 32) {
#pragma unroll
        for (int r = 0; r < 4; r++) {
            int s = r * 256 + t;
            int row = s >> 3, q = s & 7;
            int m = bm + row; if (m >= NN) m = NN - 1;
            int kg = k0 + q * 4;
            const float* ap = (kg < 128) ? (g_agg1 + (size_t)m * 128 + kg)
                                         : (x + (size_t)m * 128 + (kg - 128));
            *(float4*)&As[row][q * 4] = *(const float4*)ap;
        }
#pragma unroll
        for (int r = 0; r < 4; r++) {
            int s = r * 256 + t;
            int kr = s >> 5, c = (s & 31) * 4;
            int kg = k0 + kr;
            const float* bp = (kg < 128) ? (W1l + (size_t)kg * 128 + c)
                                         : (W1r + (size_t)(kg - 128) * 128 + c);
            *(float4*)&Bs[kr][c] = *(const float4*)bp;
        }
        __syncthreads();
#pragma unroll
        for (int ks = 0; ks < 4; ks++) {
            int kb = ks * 8;
            uint32_t ahi[2][4], alo[2][4];
#pragma unroll
            for (int mt = 0; mt < 2; mt++) {
                int rb = wm * 32 + mt * 16;
                split_tf32(As[rb + gid][kb + tig],     ahi[mt][0], alo[mt][0]);
                split_tf32(As[rb + gid + 8][kb + tig], ahi[mt][1], alo[mt][1]);
                split_tf32(As[rb + gid][kb + tig + 4],     ahi[mt][2], alo[mt][2]);
                split_tf32(As[rb + gid + 8][kb + tig + 4], ahi[mt][3], alo[mt][3]);
            }
#pragma unroll
            for (int nt = 0; nt < 8; nt++) {
                int cb = wn * 64 + nt * 8;
                uint32_t b0h, b0l, b1h, b1l;
                split_tf32(Bs[kb + tig][cb + gid],     b0h, b0l);
                split_tf32(Bs[kb + tig + 4][cb + gid], b1h, b1l);
#pragma unroll
                for (int mt = 0; mt < 2; mt++) {
                    mma_tf32(d[mt][nt], ahi[mt], b0h, b1h);
                    mma_tf32(d[mt][nt], alo[mt], b0h, b1h);
                    mma_tf32(d[mt][nt], ahi[mt], b0l, b1l);
                }
            }
        }
        __syncthreads();
    }

#pragma unroll
    for (int mt = 0; mt < 2; mt++) {
        int r0 = bm + wm * 32 + mt * 16 + gid;
#pragma unroll
        for (int nt = 0; nt < 8; nt++) {
            int col = wn * 64 + nt * 8 + 2 * tig;
            float bb0 = b1[col], bb1 = b1[col + 1];
            if (r0 < NN) {
                float2 o;
                o.x = fmaxf(d[mt][nt][0] + bb0, 0.f);
                o.y = fmaxf(d[mt][nt][1] + bb1, 0.f);
                *(float2*)&g_h[(size_t)r0 * 128 + col] = o;
            }
            if (r0 + 8 < NN) {
                float2 o;
                o.x = fmaxf(d[mt][nt][2] + bb0, 0.f);
                o.y = fmaxf(d[mt][nt][3] + bb1, 0.f);
                *(float2*)&g_h[(size_t)(r0 + 8) * 128 + col] = o;
            }
        }
    }
}

// ---------------- GEMM2: C = h @ [W2_l | W2_r]  ([50k,128]@[128,80]) ----------------
__global__ __launch_bounds__(256) void k_gemm2(const float* __restrict__ W2l,
                                               const float* __restrict__ W2r) {
    __shared__ float As[128][36];
    __shared__ float Bs[32][88];
    int t = threadIdx.x;
    int warp = t >> 5, lane = t & 31;
    int gid = lane >> 2, tig = lane & 3;
    int wm = warp >> 1, wn = warp & 1;
    int bm = blockIdx.x * 128;

    float d[2][5][4];
#pragma unroll
    for (int mt = 0; mt < 2; mt++)
#pragma unroll
        for (int nt = 0; nt < 5; nt++)
#pragma unroll
            for (int q = 0; q < 4; q++) d[mt][nt][q] = 0.f;

    for (int k0 = 0; k0 < 128; k0 += 32) {
#pragma unroll
        for (int r = 0; r < 4; r++) {
            int s = r * 256 + t;
            int row = s >> 3, q = s & 7;
            int m = bm + row; if (m >= NN) m = NN - 1;
            int kg = k0 + q * 4;
            *(float4*)&As[row][q * 4] = *(const float4*)(g_h + (size_t)m * 128 + kg);
        }
        for (int s = t; s < 640; s += 256) {
            int kr = s / 20, c = (s % 20) * 4;
            int kg = k0 + kr;
            const float* bp = (c < 40) ? (W2l + (size_t)kg * 40 + c)
                                       : (W2r + (size_t)kg * 40 + (c - 40));
            *(float4*)&Bs[kr][c] = *(const float4*)bp;
        }
        __syncthreads();
#pragma unroll
        for (int ks = 0; ks < 4; ks++) {
            int kb = ks * 8;
            uint32_t ahi[2][4], alo[2][4];
#pragma unroll
            for (int mt = 0; mt < 2; mt++) {
                int rb = wm * 32 + mt * 16;
                split_tf32(As[rb + gid][kb + tig],     ahi[mt][0], alo[mt][0]);
                split_tf32(As[rb + gid + 8][kb + tig], ahi[mt][1], alo[mt][1]);
                split_tf32(As[rb + gid][kb + tig + 4],     ahi[mt][2], alo[mt][2]);
                split_tf32(As[rb + gid + 8][kb + tig + 4], ahi[mt][3], alo[mt][3]);
            }
#pragma unroll
            for (int nt = 0; nt < 5; nt++) {
                int cb = wn * 40 + nt * 8;
                uint32_t b0h, b0l, b1h, b1l;
                split_tf32(Bs[kb + tig][cb + gid],     b0h, b0l);
                split_tf32(Bs[kb + tig + 4][cb + gid], b1h, b1l);
#pragma unroll
                for (int mt = 0; mt < 2; mt++) {
                    mma_tf32(d[mt][nt], ahi[mt], b0h, b1h);
                    mma_tf32(d[mt][nt], alo[mt], b0h, b1h);
                    mma_tf32(d[mt][nt], ahi[mt], b0l, b1l);
                }
            }
        }
        __syncthreads();
    }

#pragma unroll
    for (int mt = 0; mt < 2; mt++) {
        int r0 = bm + wm * 32 + mt * 16 + gid;
#pragma unroll
        for (int nt = 0; nt < 5; nt++) {
            int col = wn * 40 + nt * 8 + 2 * tig;
            if (r0 < NN) {
                float2 o = make_float2(d[mt][nt][0], d[mt][nt][1]);
                *(float2*)&g_C[(size_t)r0 * 80 + col] = o;
            }
            if (r0 + 8 < NN) {
                float2 o = make_float2(d[mt][nt][2], d[mt][nt][3]);
                *(float2*)&g_C[(size_t)(r0 + 8) * 80 + col] = o;
            }
        }
    }
}

// ---------------- layer-2 aggregation + epilogue ----------------
__global__ void k_final(const float* __restrict__ b2, float* __restrict__ out) {
    int gt = blockIdx.x * blockDim.x + threadIdx.x;
    int w = gt >> 5;
    int lane = gt & 31;
    if (w >= NN) return;
    int s0 = g_row[w], s1 = g_row[w + 1];
    if (lane < 20) {
        float2 acc = make_float2(0.f, 0.f);
        int i = s0;
        for (; i + 4 <= s1; i += 4) {
            int sa = g_src[i], sb = g_src[i + 1], sc = g_src[i + 2], sd = g_src[i + 3];
            float2 a = *(const float2*)&g_C[(size_t)sa * 80 + lane * 2];
            float2 b = *(const float2*)&g_C[(size_t)sb * 80 + lane * 2];
            float2 c = *(const float2*)&g_C[(size_t)sc * 80 + lane * 2];
            float2 e = *(const float2*)&g_C[(size_t)sd * 80 + lane * 2];
            acc.x += a.x + b.x + c.x + e.x;
            acc.y += a.y + b.y + c.y + e.y;
        }
        for (; i < s1; i++) {
            int sa = g_src[i];
            float2 a = *(const float2*)&g_C[(size_t)sa * 80 + lane * 2];
            acc.x += a.x; acc.y += a.y;
        }
        int cnt = s1 - s0; if (cnt < 1) cnt = 1;
        float sc = 1.0f / (float)cnt;
        float2 r = *(const float2*)&g_C[(size_t)w * 80 + 40 + lane * 2];
        float2 bb = *(const float2*)&b2[lane * 2];
        float2 o;
        o.x = acc.x * sc + r.x + bb.x;
        o.y = acc.y * sc + r.y + bb.y;
        *(float2*)&out[(size_t)w * 40 + lane * 2] = o;
    }
}

// ---------------- launcher ----------------
extern "C" void kernel_launch(void* const* d_in, const int* in_sizes, int n_in,
                              void* d_out, int out_size) {
    const float* x   = (const float*)d_in[0];
    const void*  ei  = d_in[1];
    const float* W1l = (const float*)d_in[2];
    const float* b1  = (const float*)d_in[3];
    const float* W1r = (const float*)d_in[4];
    const float* W2l = (const float*)d_in[5];
    const float* b2  = (const float*)d_in[6];
    const float* W2r = (const float*)d_in[7];
    float* out = (float*)d_out;

    k_zero_detect<<<NBLK, 256>>>((const int*)ei);
    k_hist<<<(NE + 255) / 256, 256>>>(ei);
    k_reduce<<<NBLK, 256>>>();
    k_scanpart<<<1, 256>>>();
    k_scanblk<<<NBLK, 256>>>();
    k_scatter<<<(NE + 255) / 256, 256>>>(ei);
    k_agg1<<<(NN + 7) / 8, 256>>>(x);
    k_gemm1<<<(NN + 127) / 128, 256>>>(x, W1l, W1r, b1);
    k_gemm2<<<(NN + 127) / 128, 256>>>(W2l, W2r);
    k_final<<<(NN + 7) / 8, 256>>>(b2, out);
}